// round 5
// baseline (speedup 1.0000x reference)
#include <cuda_runtime.h>
#include <cuda_bf16.h>
#include <math.h>
#include <stdint.h>

#define LL 4096
#define CC 256
#define NBATCH 2
#define THRV 0.2f
#define MAXC 4096
#define BKPAD 264   // 256 + 8 bf16 pad -> conflict-free fragment LDS

// ------------------------- device scratch (statically allocated) ------------
static __device__ float         g_conf[(size_t)NBATCH * LL * LL];       // 128 MB
static __device__ __nv_bfloat16 g_bf0[NBATCH * LL * CC];
static __device__ __nv_bfloat16 g_bf1[NBATCH * LL * CC];
static __device__ float         g_rowPart[NBATCH * 32 * LL];
static __device__ float         g_colPart[NBATCH * 32 * LL];
static __device__ float         g_invR[NBATCH * LL];
static __device__ float         g_invC[NBATCH * LL];
static __device__ float         g_s0p[NBATCH * LL * 96];   // pooled-96 masked features
static __device__ float         g_s1p[NBATCH * LL * 96];
static __device__ int           g_candCount;
static __device__ int           g_cand[MAXC];

// ------------------------- kernel 0: zero scratch ---------------------------
__global__ void k_zero() {
    int i = blockIdx.x * blockDim.x + threadIdx.x;
    const int tot = NBATCH * LL * 96;
    if (i < tot) { g_s0p[i] = 0.f; g_s1p[i] = 0.f; }
    if (i == 0) g_candCount = 0;
}

// ------------------------- kernel 1: f32 -> bf16 ----------------------------
__global__ void k_convert(const float* __restrict__ f0, const float* __restrict__ f1) {
    int i = blockIdx.x * blockDim.x + threadIdx.x;
    if (i < NBATCH * LL * CC) {
        g_bf0[i] = __float2bfloat16(f0[i]);
        g_bf1[i] = __float2bfloat16(f1[i]);
    }
}

// ------------------------- kernel 2: GEMM + fused exp partial sums ----------
// conf[n][l][s] = dot(feat0[n][l], feat1[n][s]) / 16
// block tile 128x128, K=256 resident in SMEM, 8 warps, warp tile 64x32,
// mma.sync.m16n8k16 bf16 -> f32.
__global__ void __launch_bounds__(256) k_gemm() {
    extern __shared__ unsigned char smraw[];
    __nv_bfloat16* As = (__nv_bfloat16*)smraw;          // [128][BKPAD]
    __nv_bfloat16* Bs = As + 128 * BKPAD;               // [128][BKPAD]

    const int n  = blockIdx.z;
    const int bx = blockIdx.x;   // s tile
    const int by = blockIdx.y;   // l tile
    const int tid = threadIdx.x;

    // load tiles: 128 rows x 256 bf16 each, as uint4 (8 bf16)
    const uint4* ga = (const uint4*)(g_bf0 + ((size_t)n * LL + (size_t)by * 128) * CC);
    const uint4* gb = (const uint4*)(g_bf1 + ((size_t)n * LL + (size_t)bx * 128) * CC);
    for (int i = tid; i < 4096; i += 256) {
        int r = i >> 5, c8 = i & 31;       // 32 uint4 per row
        uint4 va = ga[r * 32 + c8];
        uint4 vb = gb[r * 32 + c8];
        *(uint4*)(As + r * BKPAD + c8 * 8) = va;
        *(uint4*)(Bs + r * BKPAD + c8 * 8) = vb;
    }
    __syncthreads();

    const int wid  = tid >> 5, lane = tid & 31;
    const int wm   = wid & 1,  wn   = wid >> 1;       // 2 (m) x 4 (n) warps
    const int m0   = wm * 64,  n0   = wn * 32;
    const int g    = lane >> 2, t   = lane & 3;

    float acc[4][4][4];
    #pragma unroll
    for (int mt = 0; mt < 4; mt++)
        #pragma unroll
        for (int nt = 0; nt < 4; nt++)
            #pragma unroll
            for (int r = 0; r < 4; r++) acc[mt][nt][r] = 0.f;

    #pragma unroll 4
    for (int kk = 0; kk < 16; kk++) {
        const int kb = kk * 16;
        unsigned a[4][4], b[4][2];
        #pragma unroll
        for (int mt = 0; mt < 4; mt++) {
            const __nv_bfloat16* base = As + (m0 + mt * 16 + g) * BKPAD + kb;
            a[mt][0] = *(const unsigned*)(base + 2 * t);
            a[mt][1] = *(const unsigned*)(base + 8 * BKPAD + 2 * t);
            a[mt][2] = *(const unsigned*)(base + 8 + 2 * t);
            a[mt][3] = *(const unsigned*)(base + 8 * BKPAD + 8 + 2 * t);
        }
        #pragma unroll
        for (int nt = 0; nt < 4; nt++) {
            const __nv_bfloat16* base = Bs + (n0 + nt * 8 + g) * BKPAD + kb;
            b[nt][0] = *(const unsigned*)(base + 2 * t);
            b[nt][1] = *(const unsigned*)(base + 8 + 2 * t);
        }
        #pragma unroll
        for (int mt = 0; mt < 4; mt++)
            #pragma unroll
            for (int nt = 0; nt < 4; nt++)
                asm volatile(
                    "mma.sync.aligned.m16n8k16.row.col.f32.bf16.bf16.f32 "
                    "{%0,%1,%2,%3}, {%4,%5,%6,%7}, {%8,%9}, {%0,%1,%2,%3};\n"
                    : "+f"(acc[mt][nt][0]), "+f"(acc[mt][nt][1]),
                      "+f"(acc[mt][nt][2]), "+f"(acc[mt][nt][3])
                    : "r"(a[mt][0]), "r"(a[mt][1]), "r"(a[mt][2]), "r"(a[mt][3]),
                      "r"(b[nt][0]), "r"(b[nt][1]));
    }

    // stage scaled tile into SMEM (f32, stride 132) for coalesced store + sums
    __syncthreads();
    float* sm = (float*)smraw;   // [128][132]
    const float SCALE = 0.0625f; // 1/sqrt(256)
    #pragma unroll
    for (int mt = 0; mt < 4; mt++) {
        #pragma unroll
        for (int nt = 0; nt < 4; nt++) {
            int r0 = m0 + mt * 16 + g;
            int c0 = n0 + nt * 8 + 2 * t;
            sm[r0 * 132 + c0]         = acc[mt][nt][0] * SCALE;
            sm[r0 * 132 + c0 + 1]     = acc[mt][nt][1] * SCALE;
            sm[(r0 + 8) * 132 + c0]   = acc[mt][nt][2] * SCALE;
            sm[(r0 + 8) * 132 + c0+1] = acc[mt][nt][3] * SCALE;
        }
    }
    __syncthreads();

    // coalesced conf store
    float* confTile = g_conf + (size_t)n * LL * LL + (size_t)(by * 128) * LL + bx * 128;
    for (int i = tid; i < 16384; i += 256) {
        int r = i >> 7, c = i & 127;
        confTile[(size_t)r * LL + c] = sm[r * 132 + c];
    }
    // fused exp partial sums (row dir = sum over s, col dir = sum over l)
    if (tid < 128) {
        float s = 0.f;
        for (int c = 0; c < 128; c++) s += expf(sm[tid * 132 + c]);
        g_rowPart[((size_t)n * 32 + bx) * LL + by * 128 + tid] = s;
    } else {
        int c = tid - 128;
        float s = 0.f;
        for (int r = 0; r < 128; r++) s += expf(sm[r * 132 + c]);
        g_colPart[((size_t)n * 32 + by) * LL + bx * 128 + c] = s;
    }
}

// ------------------------- kernel 3: reduce partials ------------------------
__global__ void k_reduce() {
    int i = blockIdx.x * blockDim.x + threadIdx.x;
    if (i >= NBATCH * LL) return;
    int n = i / LL, l = i % LL;
    float sr = 0.f, sc = 0.f;
    #pragma unroll
    for (int tI = 0; tI < 32; tI++) {
        sr += g_rowPart[((size_t)n * 32 + tI) * LL + l];
        sc += g_colPart[((size_t)n * 32 + tI) * LL + l];
    }
    g_invR[i] = 1.0f / sr;
    g_invC[i] = 1.0f / sc;
}

// ------------------------- kernel 4: candidate scan (p > THR) ---------------
__global__ void k_scan() {
    const unsigned tot4 = (unsigned)NBATCH * LL * LL / 4;  // 8,388,608
    unsigned stride = gridDim.x * blockDim.x;
    const float4* cf = (const float4*)g_conf;
    for (unsigned i4 = blockIdx.x * blockDim.x + threadIdx.x; i4 < tot4; i4 += stride) {
        float4 v = cf[i4];
        unsigned e0 = i4 * 4u;
        int n = (int)(e0 >> 24);
        int l = (int)((e0 >> 12) & 4095u);
        int s = (int)(e0 & 4095u);
        float ir = g_invR[n * LL + l];
        float pv[4];
        {
            float e;
            e = expf(v.x); pv[0] = e * e * ir * g_invC[n * LL + s + 0];
            e = expf(v.y); pv[1] = e * e * ir * g_invC[n * LL + s + 1];
            e = expf(v.z); pv[2] = e * e * ir * g_invC[n * LL + s + 2];
            e = expf(v.w); pv[3] = e * e * ir * g_invC[n * LL + s + 3];
        }
        #pragma unroll
        for (int j = 0; j < 4; j++) {
            if (pv[j] > THRV) {
                int idx = atomicAdd(&g_candCount, 1);
                if (idx < MAXC) g_cand[idx] = (int)(e0 + j);
            }
        }
    }
}

// ------------------------- kernel 5: resolve rare matches -------------------
// For candidate (n,l,s): verify mutual-max, then compute fea (unfold path),
// pool to 96 dims and accumulate /L into s0p[n][l] and s1p[n][s].
__device__ void accum_fea_pooled(const float* __restrict__ Xn, int loc,
                                 float* __restrict__ dst96) {
    __shared__ float sem[9];
    __shared__ float fea[CC];
    __shared__ float red2[CC];
    int c = threadIdx.x;
    int h = loc >> 6, w = loc & 63;
    float xlc = Xn[(size_t)loc * CC + c];
    float uv[9];
    #pragma unroll
    for (int w9 = 0; w9 < 9; w9++) {
        int dy = w9 / 3 - 1, dx = w9 % 3 - 1;
        int hh = h + dy, ww = w + dx;
        float u = 0.f;
        if (hh >= 0 && hh < 64 && ww >= 0 && ww < 64)
            u = Xn[(size_t)c * 4096 + hh * 64 + ww];   // raw (C,H,W) reinterpretation
        uv[w9] = u;
    }
    for (int w9 = 0; w9 < 9; w9++) {
        red2[c] = xlc * uv[w9];
        __syncthreads();
        for (int off = 128; off > 0; off >>= 1) {
            if (c < off) red2[c] += red2[c + off];
            __syncthreads();
        }
        if (c == 0) sem[w9] = red2[0] * (1.0f / CC);
        __syncthreads();
    }
    float f = 0.f;
    #pragma unroll
    for (int w9 = 0; w9 < 9; w9++) f += uv[w9] * sem[w9];
    fea[c] = f;
    __syncthreads();
    if (c < 96) {
        int st = (c * 256) / 96, en = ((c + 1) * 256 + 95) / 96;
        float s = 0.f;
        for (int q = st; q < en; q++) s += fea[q];
        atomicAdd(&dst96[c], (s / (float)(en - st)) * (1.0f / (float)LL));
    }
    __syncthreads();
}

__global__ void k_match(const float* __restrict__ f0, const float* __restrict__ f1) {
    __shared__ float red[256];
    int count = g_candCount;
    if (count > MAXC) count = MAXC;
    for (int ci = blockIdx.x; ci < count; ci += gridDim.x) {
        int id = g_cand[ci];
        int n = id >> 24, l = (id >> 12) & 4095, s = id & 4095;
        const float* confN = g_conf + ((size_t)n << 24);
        float ir = g_invR[n * LL + l], ics = g_invC[n * LL + s];
        float c0 = confN[(size_t)l * LL + s];
        float e0 = expf(c0);
        float p0 = e0 * e0 * ir * ics;

        // row max over s'
        float m = -1e30f;
        for (int j = threadIdx.x; j < LL; j += 256) {
            float cc = confN[(size_t)l * LL + j];
            float e = expf(cc);
            m = fmaxf(m, e * e * ir * g_invC[n * LL + j]);
        }
        red[threadIdx.x] = m; __syncthreads();
        for (int off = 128; off > 0; off >>= 1) {
            if (threadIdx.x < off) red[threadIdx.x] = fmaxf(red[threadIdx.x], red[threadIdx.x + off]);
            __syncthreads();
        }
        float rowmax = red[0]; __syncthreads();

        // col max over l'
        m = -1e30f;
        for (int j = threadIdx.x; j < LL; j += 256) {
            float cc = confN[(size_t)j * LL + s];
            float e = expf(cc);
            m = fmaxf(m, e * e * g_invR[n * LL + j] * ics);
        }
        red[threadIdx.x] = m; __syncthreads();
        for (int off = 128; off > 0; off >>= 1) {
            if (threadIdx.x < off) red[threadIdx.x] = fmaxf(red[threadIdx.x], red[threadIdx.x + off]);
            __syncthreads();
        }
        float colmax = red[0]; __syncthreads();

        bool match = (p0 > THRV) && (p0 >= rowmax * (1.f - 1e-6f)) && (p0 >= colmax * (1.f - 1e-6f));
        if (match) {
            // s0[l] += fea1[s]/L ;  s1[s] += fea0[l]/L
            accum_fea_pooled(f1 + (size_t)n * LL * CC, s, g_s0p + ((size_t)n * LL + l) * 96);
            accum_fea_pooled(f0 + (size_t)n * LL * CC, l, g_s1p + ((size_t)n * LL + s) * 96);
        }
        __syncthreads();
    }
}

// ------------------------- kernel 6: pool + concat + LayerNorm --------------
__global__ void k_out(const float* __restrict__ f0, const float* __restrict__ f1,
                      const float* __restrict__ lw, const float* __restrict__ lb,
                      float* __restrict__ out) {
    __shared__ float frow[CC];
    int l = blockIdx.x, b = blockIdx.y;          // b in [0,4)
    int n = b & 1;
    const float* X  = (b < 2 ? f0 : f1) + ((size_t)n * LL + l) * CC;
    const float* sp = (b < 2 ? g_s0p : g_s1p) + ((size_t)n * LL + l) * 96;
    int t = threadIdx.x;
    frow[t] = X[t];
    __syncthreads();

    float val;
    if (t < 160) {
        int st = (t * 256) / 160, en = ((t + 1) * 256 + 159) / 160;
        float s = 0.f;
        for (int q = st; q < en; q++) s += frow[q];
        val = s / (float)(en - st);
    } else {
        val = sp[t - 160];
    }
    __syncthreads();

    // mean
    frow[t] = val; __syncthreads();
    for (int off = 128; off > 0; off >>= 1) {
        if (t < off) frow[t] += frow[t + off];
        __syncthreads();
    }
    float mean = frow[0] * (1.0f / CC);
    __syncthreads();
    // variance (biased)
    float d = val - mean;
    frow[t] = d * d; __syncthreads();
    for (int off = 128; off > 0; off >>= 1) {
        if (t < off) frow[t] += frow[t + off];
        __syncthreads();
    }
    float var = frow[0] * (1.0f / CC);
    float r = rsqrtf(var + 1e-5f);
    out[((size_t)b * LL + l) * CC + t] = d * r * lw[t] + lb[t];
}

// ------------------------- launch ------------------------------------------
extern "C" void kernel_launch(void* const* d_in, const int* in_sizes, int n_in,
                              void* d_out, int out_size) {
    const float* f0 = (const float*)d_in[0];
    const float* f1 = (const float*)d_in[1];
    const float* lw = (const float*)d_in[2];
    const float* lb = (const float*)d_in[3];
    float* out = (float*)d_out;
    (void)in_sizes; (void)n_in; (void)out_size;

    cudaFuncSetAttribute(k_gemm, cudaFuncAttributeMaxDynamicSharedMemorySize, 135168);

    k_zero<<<(NBATCH * LL * 96 + 511) / 512, 512>>>();
    k_convert<<<(NBATCH * LL * CC + 511) / 512, 512>>>(f0, f1);
    k_gemm<<<dim3(32, 32, NBATCH), 256, 135168>>>();
    k_reduce<<<(NBATCH * LL + 255) / 256, 256>>>();
    k_scan<<<8192, 256>>>();
    k_match<<<32, 256>>>(f0, f1);
    k_out<<<dim3(LL, 4), 256>>>(f0, f1, lw, lb, out);
}

// round 6
// speedup vs baseline: 1.7704x; 1.7704x over previous
#include <cuda_runtime.h>
#include <cuda_bf16.h>
#include <math.h>
#include <stdint.h>

#define LL 4096
#define CC 256
#define NBATCH 2
#define THRV 0.2f
#define MAXC 4096
#define APAD 72                    // bf16 per smem row (64 + 8 pad)
#define STG_STRIDE (128 * APAD)    // bf16 elements per stage buffer

// ------------------------- device scratch (statically allocated) ------------
static __device__ __nv_bfloat16 g_confh[(size_t)NBATCH * LL * LL];   // 64 MB
static __device__ __nv_bfloat16 g_bf0[NBATCH * LL * CC];
static __device__ __nv_bfloat16 g_bf1[NBATCH * LL * CC];
static __device__ float         g_rowPart[NBATCH * 32 * LL];
static __device__ float         g_colPart[NBATCH * 32 * LL];
static __device__ float         g_invR[NBATCH * LL];
static __device__ float         g_invC[NBATCH * LL];
static __device__ int           g_minR[NBATCH];
static __device__ int           g_minC[NBATCH];
static __device__ float         g_s0p[NBATCH * LL * 96];
static __device__ float         g_s1p[NBATCH * LL * 96];
static __device__ int           g_candCount;
static __device__ int           g_cand[MAXC];

__device__ __forceinline__ void cp16(__nv_bfloat16* smem, const __nv_bfloat16* gmem) {
    uint32_t s = (uint32_t)__cvta_generic_to_shared(smem);
    asm volatile("cp.async.cg.shared.global [%0], [%1], 16;\n" :: "r"(s), "l"(gmem));
}

// ------------------------- kernel 0: zero scratch ---------------------------
__global__ void k_zero() {
    int i = blockIdx.x * blockDim.x + threadIdx.x;
    const int tot = NBATCH * LL * 96;
    if (i < tot) { g_s0p[i] = 0.f; g_s1p[i] = 0.f; }
    if (i == 0) {
        g_candCount = 0;
        #pragma unroll
        for (int n = 0; n < NBATCH; n++) {
            g_minR[n] = 0x7F800000;   // +inf
            g_minC[n] = 0x7F800000;
        }
    }
}

// ------------------------- kernel 1: f32 -> bf16 (vectorized) ---------------
__global__ void k_convert(const float4* __restrict__ f0, const float4* __restrict__ f1) {
    int i = blockIdx.x * blockDim.x + threadIdx.x;
    if (i < NBATCH * LL * CC / 4) {
        float4 a = f0[i], b = f1[i];
        __nv_bfloat162* o0 = (__nv_bfloat162*)g_bf0;
        __nv_bfloat162* o1 = (__nv_bfloat162*)g_bf1;
        o0[2 * i]     = __float22bfloat162_rn(make_float2(a.x, a.y));
        o0[2 * i + 1] = __float22bfloat162_rn(make_float2(a.z, a.w));
        o1[2 * i]     = __float22bfloat162_rn(make_float2(b.x, b.y));
        o1[2 * i + 1] = __float22bfloat162_rn(make_float2(b.z, b.w));
    }
}

// ------------------------- kernel 2: pipelined GEMM + bf16 conf + sums ------
// conf[n][l][s] = dot(feat0[n][l], feat1[n][s]) / 16, stored bf16.
// 128x128 block tile, BK=64, 2-stage cp.async double buffer, 2 CTAs/SM.
__global__ void __launch_bounds__(256, 2) k_gemm() {
    extern __shared__ __nv_bfloat16 sh[];   // 2xA(128x72) + 2xB(128x72) = 72 KB

    const int n  = blockIdx.z;
    const int bx = blockIdx.x;   // s tile
    const int by = blockIdx.y;   // l tile
    const int tid = threadIdx.x;

    const __nv_bfloat16* gA0 = g_bf0 + ((size_t)n * LL + (size_t)by * 128) * CC;
    const __nv_bfloat16* gB0 = g_bf1 + ((size_t)n * LL + (size_t)bx * 128) * CC;

    auto load_stage = [&](int kc, int buf) {
        __nv_bfloat16* As = sh + buf * STG_STRIDE;
        __nv_bfloat16* Bs = sh + 2 * STG_STRIDE + buf * STG_STRIDE;
        const __nv_bfloat16* gA = gA0 + kc * 64;
        const __nv_bfloat16* gB = gB0 + kc * 64;
        #pragma unroll
        for (int it = 0; it < 4; it++) {
            int ch = tid + it * 256;           // 0..1023
            int r = ch >> 3, c = (ch & 7) * 8; // 8x16B chunks per 64-col row
            cp16(As + r * APAD + c, gA + (size_t)r * CC + c);
            cp16(Bs + r * APAD + c, gB + (size_t)r * CC + c);
        }
        asm volatile("cp.async.commit_group;\n" ::: "memory");
    };

    const int wid  = tid >> 5, lane = tid & 31;
    const int wm   = wid & 1,  wn   = wid >> 1;       // 2 (m) x 4 (n) warps
    const int m0   = wm * 64,  n0   = wn * 32;
    const int g    = lane >> 2, t   = lane & 3;

    float acc[4][4][4] = {};

    load_stage(0, 0);

    #pragma unroll
    for (int kc = 0; kc < 4; kc++) {
        if (kc < 3) {
            load_stage(kc + 1, (kc + 1) & 1);
            asm volatile("cp.async.wait_group 1;\n" ::: "memory");
        } else {
            asm volatile("cp.async.wait_group 0;\n" ::: "memory");
        }
        __syncthreads();

        const __nv_bfloat16* As = sh + (kc & 1) * STG_STRIDE;
        const __nv_bfloat16* Bs = sh + 2 * STG_STRIDE + (kc & 1) * STG_STRIDE;

        #pragma unroll
        for (int ks = 0; ks < 4; ks++) {
            const int kb = ks * 16;
            unsigned a[4][4], b[4][2];
            #pragma unroll
            for (int mt = 0; mt < 4; mt++) {
                const __nv_bfloat16* base = As + (m0 + mt * 16 + g) * APAD + kb;
                a[mt][0] = *(const unsigned*)(base + 2 * t);
                a[mt][1] = *(const unsigned*)(base + 8 * APAD + 2 * t);
                a[mt][2] = *(const unsigned*)(base + 8 + 2 * t);
                a[mt][3] = *(const unsigned*)(base + 8 * APAD + 8 + 2 * t);
            }
            #pragma unroll
            for (int nt = 0; nt < 4; nt++) {
                const __nv_bfloat16* base = Bs + (n0 + nt * 8 + g) * APAD + kb;
                b[nt][0] = *(const unsigned*)(base + 2 * t);
                b[nt][1] = *(const unsigned*)(base + 8 + 2 * t);
            }
            #pragma unroll
            for (int mt = 0; mt < 4; mt++)
                #pragma unroll
                for (int nt = 0; nt < 4; nt++)
                    asm volatile(
                        "mma.sync.aligned.m16n8k16.row.col.f32.bf16.bf16.f32 "
                        "{%0,%1,%2,%3}, {%4,%5,%6,%7}, {%8,%9}, {%0,%1,%2,%3};\n"
                        : "+f"(acc[mt][nt][0]), "+f"(acc[mt][nt][1]),
                          "+f"(acc[mt][nt][2]), "+f"(acc[mt][nt][3])
                        : "r"(a[mt][0]), "r"(a[mt][1]), "r"(a[mt][2]), "r"(a[mt][3]),
                          "r"(b[nt][0]), "r"(b[nt][1]));
        }
        __syncthreads();
    }

    // ---- epilogue: stage scaled bf16 tile [128][136], store + fused sums ----
    __nv_bfloat16* st = sh;   // reuse (34.8 KB needed, 72 KB available)
    const float SC = 0.0625f; // 1/sqrt(256)
    #pragma unroll
    for (int mt = 0; mt < 4; mt++) {
        #pragma unroll
        for (int nt = 0; nt < 4; nt++) {
            int r0 = m0 + mt * 16 + g;
            int c0 = n0 + nt * 8 + 2 * t;
            *(__nv_bfloat162*)(st + r0 * 136 + c0) =
                __float22bfloat162_rn(make_float2(acc[mt][nt][0] * SC, acc[mt][nt][1] * SC));
            *(__nv_bfloat162*)(st + (r0 + 8) * 136 + c0) =
                __float22bfloat162_rn(make_float2(acc[mt][nt][2] * SC, acc[mt][nt][3] * SC));
        }
    }
    __syncthreads();

    // coalesced bf16 conf store (uint4 = 8 bf16)
    __nv_bfloat16* confT = g_confh + (size_t)n * LL * LL + (size_t)(by * 128) * LL + bx * 128;
    for (int i = tid; i < 2048; i += 256) {
        int r = i >> 4, c = (i & 15) * 8;
        *(uint4*)(confT + (size_t)r * LL + c) = *(const uint4*)(st + r * 136 + c);
    }
    // fused exp partial sums over the bf16-rounded conf (consistent with scan)
    if (tid < 128) {
        float s = 0.f;
        for (int c = 0; c < 128; c++) s += expf(__bfloat162float(st[tid * 136 + c]));
        g_rowPart[((size_t)n * 32 + bx) * LL + by * 128 + tid] = s;
    } else {
        int c = tid - 128;
        float s = 0.f;
        for (int r = 0; r < 128; r++) s += expf(__bfloat162float(st[r * 136 + c]));
        g_colPart[((size_t)n * 32 + by) * LL + bx * 128 + c] = s;
    }
}

// ------------------------- kernel 3: reduce partials + mins -----------------
__global__ void k_reduce() {
    int i = blockIdx.x * blockDim.x + threadIdx.x;
    if (i >= NBATCH * LL) return;
    int n = i / LL, l = i % LL;
    float sr = 0.f, sc = 0.f;
    #pragma unroll
    for (int tI = 0; tI < 32; tI++) {
        sr += g_rowPart[((size_t)n * 32 + tI) * LL + l];
        sc += g_colPart[((size_t)n * 32 + tI) * LL + l];
    }
    g_invR[i] = 1.0f / sr;
    g_invC[i] = 1.0f / sc;
    // warp-level min, then one atomic per warp (n is warp-uniform: 4096 % 32 == 0)
    int rb = __float_as_int(sr), cb = __float_as_int(sc);  // positive floats: int order
    #pragma unroll
    for (int off = 16; off > 0; off >>= 1) {
        rb = min(rb, __shfl_xor_sync(0xffffffffu, rb, off));
        cb = min(cb, __shfl_xor_sync(0xffffffffu, cb, off));
    }
    if ((threadIdx.x & 31) == 0) {
        atomicMin(&g_minR[n], rb);
        atomicMin(&g_minC[n], cb);
    }
}

// ------------------------- kernel 4: screened candidate scan ----------------
// conservative screen: p = e^{2c}/(R_l C_s) <= e^{2c}/(Rmin Cmin); entries with
// c <= 0.5*ln(THR*Rmin*Cmin) can never exceed THR.
__global__ void k_scan() {
    float cthr[NBATCH];
    #pragma unroll
    for (int n = 0; n < NBATCH; n++) {
        float rm = __int_as_float(g_minR[n]);
        float cm = __int_as_float(g_minC[n]);
        cthr[n] = 0.5f * logf(THRV * rm * cm);
    }
    const unsigned tot8 = (unsigned)NBATCH * LL * (LL / 8);   // 4,194,304 uint4
    unsigned stride = gridDim.x * blockDim.x;
    const uint4* cf = (const uint4*)g_confh;
    for (unsigned i8 = blockIdx.x * blockDim.x + threadIdx.x; i8 < tot8; i8 += stride) {
        uint4 v = cf[i8];
        unsigned e0 = i8 * 8u;
        int n = (int)(e0 >> 24);
        const __nv_bfloat16* h = (const __nv_bfloat16*)&v;
        float thr = cthr[n];
        float cv[8];
        float mx = -1e30f;
        #pragma unroll
        for (int j = 0; j < 8; j++) { cv[j] = __bfloat162float(h[j]); mx = fmaxf(mx, cv[j]); }
        if (mx > thr) {   // rare path
            int l = (int)((e0 >> 12) & 4095u);
            int s = (int)(e0 & 4095u);
            float ir = g_invR[n * LL + l];
            #pragma unroll
            for (int j = 0; j < 8; j++) {
                if (cv[j] > thr) {
                    float e = expf(cv[j]);
                    float p = e * e * ir * g_invC[n * LL + s + j];
                    if (p > THRV) {
                        int idx = atomicAdd(&g_candCount, 1);
                        if (idx < MAXC) g_cand[idx] = (int)(e0 + j);
                    }
                }
            }
        }
    }
}

// ------------------------- kernel 5: resolve rare matches -------------------
__device__ void accum_fea_pooled(const float* __restrict__ Xn, int loc,
                                 float* __restrict__ dst96) {
    __shared__ float sem[9];
    __shared__ float fea[CC];
    __shared__ float red2[CC];
    int c = threadIdx.x;
    int h = loc >> 6, w = loc & 63;
    float xlc = Xn[(size_t)loc * CC + c];
    float uv[9];
    #pragma unroll
    for (int w9 = 0; w9 < 9; w9++) {
        int dy = w9 / 3 - 1, dx = w9 % 3 - 1;
        int hh = h + dy, ww = w + dx;
        float u = 0.f;
        if (hh >= 0 && hh < 64 && ww >= 0 && ww < 64)
            u = Xn[(size_t)c * 4096 + hh * 64 + ww];   // raw (C,H,W) reinterpretation
        uv[w9] = u;
    }
    for (int w9 = 0; w9 < 9; w9++) {
        red2[c] = xlc * uv[w9];
        __syncthreads();
        for (int off = 128; off > 0; off >>= 1) {
            if (c < off) red2[c] += red2[c + off];
            __syncthreads();
        }
        if (c == 0) sem[w9] = red2[0] * (1.0f / CC);
        __syncthreads();
    }
    float f = 0.f;
    #pragma unroll
    for (int w9 = 0; w9 < 9; w9++) f += uv[w9] * sem[w9];
    fea[c] = f;
    __syncthreads();
    if (c < 96) {
        int st = (c * 256) / 96, en = ((c + 1) * 256 + 95) / 96;
        float s = 0.f;
        for (int q = st; q < en; q++) s += fea[q];
        atomicAdd(&dst96[c], (s / (float)(en - st)) * (1.0f / (float)LL));
    }
    __syncthreads();
}

__global__ void k_match(const float* __restrict__ f0, const float* __restrict__ f1) {
    __shared__ float red[256];
    int count = g_candCount;
    if (count > MAXC) count = MAXC;
    for (int ci = blockIdx.x; ci < count; ci += gridDim.x) {
        int id = g_cand[ci];
        int n = id >> 24, l = (id >> 12) & 4095, s = id & 4095;
        const __nv_bfloat16* confN = g_confh + ((size_t)n << 24);
        float ir = g_invR[n * LL + l], ics = g_invC[n * LL + s];
        float c0 = __bfloat162float(confN[(size_t)l * LL + s]);
        float e0 = expf(c0);
        float p0 = e0 * e0 * ir * ics;

        // row max over s'
        float m = -1e30f;
        for (int j = threadIdx.x; j < LL; j += 256) {
            float cc = __bfloat162float(confN[(size_t)l * LL + j]);
            float e = expf(cc);
            m = fmaxf(m, e * e * ir * g_invC[n * LL + j]);
        }
        red[threadIdx.x] = m; __syncthreads();
        for (int off = 128; off > 0; off >>= 1) {
            if (threadIdx.x < off) red[threadIdx.x] = fmaxf(red[threadIdx.x], red[threadIdx.x + off]);
            __syncthreads();
        }
        float rowmax = red[0]; __syncthreads();

        // col max over l'
        m = -1e30f;
        for (int j = threadIdx.x; j < LL; j += 256) {
            float cc = __bfloat162float(confN[(size_t)j * LL + s]);
            float e = expf(cc);
            m = fmaxf(m, e * e * g_invR[n * LL + j] * ics);
        }
        red[threadIdx.x] = m; __syncthreads();
        for (int off = 128; off > 0; off >>= 1) {
            if (threadIdx.x < off) red[threadIdx.x] = fmaxf(red[threadIdx.x], red[threadIdx.x + off]);
            __syncthreads();
        }
        float colmax = red[0]; __syncthreads();

        bool match = (p0 > THRV) && (p0 >= rowmax * (1.f - 1e-6f)) && (p0 >= colmax * (1.f - 1e-6f));
        if (match) {
            accum_fea_pooled(f1 + (size_t)n * LL * CC, s, g_s0p + ((size_t)n * LL + l) * 96);
            accum_fea_pooled(f0 + (size_t)n * LL * CC, l, g_s1p + ((size_t)n * LL + s) * 96);
        }
        __syncthreads();
    }
}

// ------------------------- kernel 6: pool + concat + LayerNorm --------------
__global__ void k_out(const float* __restrict__ f0, const float* __restrict__ f1,
                      const float* __restrict__ lw, const float* __restrict__ lb,
                      float* __restrict__ out) {
    __shared__ float frow[CC];
    int l = blockIdx.x, b = blockIdx.y;          // b in [0,4)
    int n = b & 1;
    const float* X  = (b < 2 ? f0 : f1) + ((size_t)n * LL + l) * CC;
    const float* sp = (b < 2 ? g_s0p : g_s1p) + ((size_t)n * LL + l) * 96;
    int t = threadIdx.x;
    frow[t] = X[t];
    __syncthreads();

    float val;
    if (t < 160) {
        int st = (t * 256) / 160, en = ((t + 1) * 256 + 159) / 160;
        float s = 0.f;
        for (int q = st; q < en; q++) s += frow[q];
        val = s / (float)(en - st);
    } else {
        val = sp[t - 160];
    }
    __syncthreads();

    frow[t] = val; __syncthreads();
    for (int off = 128; off > 0; off >>= 1) {
        if (t < off) frow[t] += frow[t + off];
        __syncthreads();
    }
    float mean = frow[0] * (1.0f / CC);
    __syncthreads();
    float d = val - mean;
    frow[t] = d * d; __syncthreads();
    for (int off = 128; off > 0; off >>= 1) {
        if (t < off) frow[t] += frow[t + off];
        __syncthreads();
    }
    float var = frow[0] * (1.0f / CC);
    float r = rsqrtf(var + 1e-5f);
    out[((size_t)b * LL + l) * CC + t] = d * r * lw[t] + lb[t];
}

// ------------------------- launch ------------------------------------------
extern "C" void kernel_launch(void* const* d_in, const int* in_sizes, int n_in,
                              void* d_out, int out_size) {
    const float* f0 = (const float*)d_in[0];
    const float* f1 = (const float*)d_in[1];
    const float* lw = (const float*)d_in[2];
    const float* lb = (const float*)d_in[3];
    float* out = (float*)d_out;
    (void)in_sizes; (void)n_in; (void)out_size;

    cudaFuncSetAttribute(k_gemm, cudaFuncAttributeMaxDynamicSharedMemorySize, 73728);

    k_zero<<<(NBATCH * LL * 96 + 511) / 512, 512>>>();
    k_convert<<<(NBATCH * LL * CC / 4 + 255) / 256, 256>>>((const float4*)f0, (const float4*)f1);
    k_gemm<<<dim3(32, 32, NBATCH), 256, 73728>>>();
    k_reduce<<<(NBATCH * LL + 255) / 256, 256>>>();
    k_scan<<<4096, 256>>>();
    k_match<<<32, 256>>>(f0, f1);
    k_out<<<dim3(LL, 4), 256>>>(f0, f1, lw, lb, out);
}

// round 12
// speedup vs baseline: 2.0872x; 1.1790x over previous
#include <cuda_runtime.h>
#include <cuda_bf16.h>
#include <math.h>
#include <stdint.h>

#define LL 4096
#define CC 256
#define NBATCH 2
#define THRV 0.2f
#define MAXC 4096
#define NTILES 2048            // 2 * 32 * 32
#define SCALEF 0.0625f         // 1/sqrt(256)
#define APAD 72                // bf16 per smem row (64 + 8 pad)
#define STG_STRIDE (128 * APAD)

// ------------------------- device scratch (statically allocated) ------------
static __device__ __nv_bfloat16 g_bf0[NBATCH * LL * CC];
static __device__ __nv_bfloat16 g_bf1[NBATCH * LL * CC];
static __device__ float         g_rowPart[NBATCH * 32 * LL];
static __device__ float         g_colPart[NBATCH * 32 * LL];
static __device__ float         g_invR[NBATCH * LL];
static __device__ float         g_invC[NBATCH * LL];
static __device__ int           g_minR[NBATCH];
static __device__ int           g_minC[NBATCH];
static __device__ float         g_tileMax[NTILES];
static __device__ int           g_tileList[NTILES];
static __device__ int           g_tileCount;
static __device__ float         g_s0p[NBATCH * LL * 96];
static __device__ float         g_s1p[NBATCH * LL * 96];
static __device__ int           g_candCount;
static __device__ int           g_cand[MAXC];

__device__ __forceinline__ void cp16(__nv_bfloat16* smem, const __nv_bfloat16* gmem) {
    uint32_t s = (uint32_t)__cvta_generic_to_shared(smem);
    asm volatile("cp.async.cg.shared.global [%0], [%1], 16;\n" :: "r"(s), "l"(gmem));
}

// ------------------------- kernel 0: zero scratch ---------------------------
__global__ void k_zero() {
    int i = blockIdx.x * blockDim.x + threadIdx.x;
    const int tot = NBATCH * LL * 96;
    if (i < tot) { g_s0p[i] = 0.f; g_s1p[i] = 0.f; }
    if (i == 0) {
        g_candCount = 0; g_tileCount = 0;
        #pragma unroll
        for (int n = 0; n < NBATCH; n++) { g_minR[n] = 0x7F800000; g_minC[n] = 0x7F800000; }
    }
}

// ------------------------- kernel 1: f32 -> bf16 ----------------------------
__global__ void k_convert(const float4* __restrict__ f0, const float4* __restrict__ f1) {
    int i = blockIdx.x * blockDim.x + threadIdx.x;
    if (i < NBATCH * LL * CC / 4) {
        float4 a = f0[i], b = f1[i];
        __nv_bfloat162* o0 = (__nv_bfloat162*)g_bf0;
        __nv_bfloat162* o1 = (__nv_bfloat162*)g_bf1;
        o0[2 * i]     = __float22bfloat162_rn(make_float2(a.x, a.y));
        o0[2 * i + 1] = __float22bfloat162_rn(make_float2(a.z, a.w));
        o1[2 * i]     = __float22bfloat162_rn(make_float2(b.x, b.y));
        o1[2 * i + 1] = __float22bfloat162_rn(make_float2(b.z, b.w));
    }
}

// ------------------------- kernel 2: GEMM, fused sums, NO conf store --------
// conf[n][l][s] = dot(feat0[n][l], feat1[n][s]) / 16 (never materialized).
// 128x128 block tile, BK=64, 2-stage cp.async double buffer, 2 CTAs/SM.
// Epilogue: stage exp(conf) f32 in smem -> row/col partial sums + tile max.
__global__ void __launch_bounds__(256, 2) k_gemm() {
    extern __shared__ __nv_bfloat16 sh[];   // 2xA(128x72) + 2xB(128x72) = 72 KB

    const int n  = blockIdx.z;
    const int bx = blockIdx.x;   // s tile
    const int by = blockIdx.y;   // l tile
    const int tid = threadIdx.x;

    const __nv_bfloat16* gA0 = g_bf0 + ((size_t)n * LL + (size_t)by * 128) * CC;
    const __nv_bfloat16* gB0 = g_bf1 + ((size_t)n * LL + (size_t)bx * 128) * CC;

    auto load_stage = [&](int kc, int buf) {
        __nv_bfloat16* As = sh + buf * STG_STRIDE;
        __nv_bfloat16* Bs = sh + 2 * STG_STRIDE + buf * STG_STRIDE;
        const __nv_bfloat16* gA = gA0 + kc * 64;
        const __nv_bfloat16* gB = gB0 + kc * 64;
        #pragma unroll
        for (int it = 0; it < 4; it++) {
            int ch = tid + it * 256;           // 0..1023
            int r = ch >> 3, c = (ch & 7) * 8; // 8x16B chunks per 64-col row
            cp16(As + r * APAD + c, gA + (size_t)r * CC + c);
            cp16(Bs + r * APAD + c, gB + (size_t)r * CC + c);
        }
        asm volatile("cp.async.commit_group;\n" ::: "memory");
    };

    const int wid  = tid >> 5, lane = tid & 31;
    const int wm   = wid & 1,  wn   = wid >> 1;       // 2 (m) x 4 (n) warps
    const int m0   = wm * 64,  n0   = wn * 32;
    const int g    = lane >> 2, t   = lane & 3;

    float acc[4][4][4] = {};

    load_stage(0, 0);

    #pragma unroll
    for (int kc = 0; kc < 4; kc++) {
        if (kc < 3) {
            load_stage(kc + 1, (kc + 1) & 1);
            asm volatile("cp.async.wait_group 1;\n" ::: "memory");
        } else {
            asm volatile("cp.async.wait_group 0;\n" ::: "memory");
        }
        __syncthreads();

        const __nv_bfloat16* As = sh + (kc & 1) * STG_STRIDE;
        const __nv_bfloat16* Bs = sh + 2 * STG_STRIDE + (kc & 1) * STG_STRIDE;

        #pragma unroll
        for (int ks = 0; ks < 4; ks++) {
            const int kb = ks * 16;
            unsigned a[4][4], b[4][2];
            #pragma unroll
            for (int mt = 0; mt < 4; mt++) {
                const __nv_bfloat16* base = As + (m0 + mt * 16 + g) * APAD + kb;
                a[mt][0] = *(const unsigned*)(base + 2 * t);
                a[mt][1] = *(const unsigned*)(base + 8 * APAD + 2 * t);
                a[mt][2] = *(const unsigned*)(base + 8 + 2 * t);
                a[mt][3] = *(const unsigned*)(base + 8 * APAD + 8 + 2 * t);
            }
            #pragma unroll
            for (int nt = 0; nt < 4; nt++) {
                const __nv_bfloat16* base = Bs + (n0 + nt * 8 + g) * APAD + kb;
                b[nt][0] = *(const unsigned*)(base + 2 * t);
                b[nt][1] = *(const unsigned*)(base + 8 + 2 * t);
            }
            #pragma unroll
            for (int mt = 0; mt < 4; mt++)
                #pragma unroll
                for (int nt = 0; nt < 4; nt++)
                    asm volatile(
                        "mma.sync.aligned.m16n8k16.row.col.f32.bf16.bf16.f32 "
                        "{%0,%1,%2,%3}, {%4,%5,%6,%7}, {%8,%9}, {%0,%1,%2,%3};\n"
                        : "+f"(acc[mt][nt][0]), "+f"(acc[mt][nt][1]),
                          "+f"(acc[mt][nt][2]), "+f"(acc[mt][nt][3])
                        : "r"(a[mt][0]), "r"(a[mt][1]), "r"(a[mt][2]), "r"(a[mt][3]),
                          "r"(b[nt][0]), "r"(b[nt][1]));
        }
        __syncthreads();
    }

    // ---- epilogue: stage exp(conf) f32 [128][133] + tile max + sums --------
    __shared__ float s_wm[8];
    float* sm = (float*)sh;    // 128*133*4 = 68.1 KB < 72 KB (mainloop done)
    float mx = -1e30f;
    #pragma unroll
    for (int mt = 0; mt < 4; mt++) {
        #pragma unroll
        for (int nt = 0; nt < 4; nt++) {
            int r0 = m0 + mt * 16 + g;
            int c0 = n0 + nt * 8 + 2 * t;
            float v0 = acc[mt][nt][0] * SCALEF, v1 = acc[mt][nt][1] * SCALEF;
            float v2 = acc[mt][nt][2] * SCALEF, v3 = acc[mt][nt][3] * SCALEF;
            mx = fmaxf(mx, fmaxf(fmaxf(v0, v1), fmaxf(v2, v3)));
            sm[r0 * 133 + c0]           = __expf(v0);
            sm[r0 * 133 + c0 + 1]       = __expf(v1);
            sm[(r0 + 8) * 133 + c0]     = __expf(v2);
            sm[(r0 + 8) * 133 + c0 + 1] = __expf(v3);
        }
    }
    #pragma unroll
    for (int o = 16; o > 0; o >>= 1) mx = fmaxf(mx, __shfl_xor_sync(0xffffffffu, mx, o));
    if (lane == 0) s_wm[wid] = mx;
    __syncthreads();
    if (tid == 0) {
        float m = s_wm[0];
        #pragma unroll
        for (int w = 1; w < 8; w++) m = fmaxf(m, s_wm[w]);
        g_tileMax[n * 1024 + by * 32 + bx] = m;
    }

    // row / col partial sums of exp(conf)
    if (tid < 128) {
        float s = 0.f;
        #pragma unroll 4
        for (int c = 0; c < 128; c++) s += sm[tid * 133 + c];
        g_rowPart[((size_t)n * 32 + bx) * LL + by * 128 + tid] = s;
    } else {
        int c = tid - 128;
        float s = 0.f;
        #pragma unroll 4
        for (int r = 0; r < 128; r++) s += sm[r * 133 + c];
        g_colPart[((size_t)n * 32 + by) * LL + bx * 128 + c] = s;
    }
}

// ------------------------- kernel 3: reduce partials + mins -----------------
__global__ void k_reduce() {   // grid 128, block 256 -> 4 threads per output
    int o   = blockIdx.x * 64 + (threadIdx.x >> 2);
    int sub = threadIdx.x & 3;
    int n = o >> 12, l = o & 4095;
    float sr = 0.f, sc = 0.f;
    #pragma unroll
    for (int t = sub; t < 32; t += 4) {
        sr += g_rowPart[((size_t)n * 32 + t) * LL + l];
        sc += g_colPart[((size_t)n * 32 + t) * LL + l];
    }
    sr += __shfl_xor_sync(0xffffffffu, sr, 1);
    sr += __shfl_xor_sync(0xffffffffu, sr, 2);
    sc += __shfl_xor_sync(0xffffffffu, sc, 1);
    sc += __shfl_xor_sync(0xffffffffu, sc, 2);
    if (sub == 0) { g_invR[o] = 1.0f / sr; g_invC[o] = 1.0f / sc; }
    int rb = __float_as_int(sr), cb = __float_as_int(sc);
    #pragma unroll
    for (int off = 16; off > 0; off >>= 1) {
        rb = min(rb, __shfl_xor_sync(0xffffffffu, rb, off));
        cb = min(cb, __shfl_xor_sync(0xffffffffu, cb, off));
    }
    if ((threadIdx.x & 31) == 0) { atomicMin(&g_minR[n], rb); atomicMin(&g_minC[n], cb); }
}

// ------------------------- kernel 4: tile screen ----------------------------
// p = e^{2c}/(R_l C_s) <= e^{2c}/(Rmin Cmin): tiles whose conf max is below
// 0.5*ln(THR*Rmin*Cmin) can contain no candidate.
__global__ void k_tilescan() {
    int i = blockIdx.x * blockDim.x + threadIdx.x;
    if (i >= NTILES) return;
    int n = i >> 10;
    float rm = __int_as_float(g_minR[n]);
    float cm = __int_as_float(g_minC[n]);
    float cthr = 0.5f * logf(THRV * rm * cm);
    if (g_tileMax[i] > cthr) {
        int idx = atomicAdd(&g_tileCount, 1);
        if (idx < NTILES) g_tileList[idx] = i;
    }
}

// ------------------------- kernel 5: rescan flagged tiles (rare) ------------
__global__ void k_rescan() {
    int count = g_tileCount; if (count > NTILES) count = NTILES;
    for (int ti = blockIdx.x; ti < count; ti += gridDim.x) {
        int tile = g_tileList[ti];
        int n = tile >> 10, by = (tile >> 5) & 31, bx = tile & 31;
        for (int el = threadIdx.x; el < 16384; el += blockDim.x) {
            int l = by * 128 + (el >> 7);
            int s = bx * 128 + (el & 127);
            const __nv_bfloat162* a = (const __nv_bfloat162*)(g_bf0 + ((size_t)n * LL + l) * CC);
            const __nv_bfloat162* b = (const __nv_bfloat162*)(g_bf1 + ((size_t)n * LL + s) * CC);
            float d = 0.f;
            #pragma unroll 8
            for (int k = 0; k < CC / 2; k++) {
                float2 av = __bfloat1622float2(a[k]);
                float2 bv = __bfloat1622float2(b[k]);
                d += av.x * bv.x + av.y * bv.y;
            }
            float e = __expf(d * SCALEF);
            float p = e * e * g_invR[n * LL + l] * g_invC[n * LL + s];
            if (p > THRV) {
                int idx = atomicAdd(&g_candCount, 1);
                if (idx < MAXC) g_cand[idx] = (n << 24) | (l << 12) | s;
            }
        }
    }
}

// ------------------------- kernel 6: resolve rare matches -------------------
__device__ void accum_fea_pooled(const float* __restrict__ Xn, int loc,
                                 float* __restrict__ dst96) {
    __shared__ float sem[9];
    __shared__ float fea[CC];
    __shared__ float red2[CC];
    int c = threadIdx.x;
    int h = loc >> 6, w = loc & 63;
    float xlc = Xn[(size_t)loc * CC + c];
    float uv[9];
    #pragma unroll
    for (int w9 = 0; w9 < 9; w9++) {
        int dy = w9 / 3 - 1, dx = w9 % 3 - 1;
        int hh = h + dy, ww = w + dx;
        float u = 0.f;
        if (hh >= 0 && hh < 64 && ww >= 0 && ww < 64)
            u = Xn[(size_t)c * 4096 + hh * 64 + ww];   // raw (C,H,W) reinterpretation
        uv[w9] = u;
    }
    for (int w9 = 0; w9 < 9; w9++) {
        red2[c] = xlc * uv[w9];
        __syncthreads();
        for (int off = 128; off > 0; off >>= 1) {
            if (c < off) red2[c] += red2[c + off];
            __syncthreads();
        }
        if (c == 0) sem[w9] = red2[0] * (1.0f / CC);
        __syncthreads();
    }
    float f = 0.f;
    #pragma unroll
    for (int w9 = 0; w9 < 9; w9++) f += uv[w9] * sem[w9];
    fea[c] = f;
    __syncthreads();
    if (c < 96) {
        int st = (c * 256) / 96, en = ((c + 1) * 256 + 95) / 96;
        float s = 0.f;
        for (int q = st; q < en; q++) s += fea[q];
        atomicAdd(&dst96[c], (s / (float)(en - st)) * (1.0f / (float)LL));
    }
    __syncthreads();
}

__global__ void k_match(const float* __restrict__ f0, const float* __restrict__ f1) {
    __shared__ float a_row[CC];
    __shared__ float b_col[CC];
    __shared__ float red[256];
    int count = g_candCount; if (count > MAXC) count = MAXC;
    for (int ci = blockIdx.x; ci < count; ci += gridDim.x) {
        int id = g_cand[ci];
        int n = id >> 24, l = (id >> 12) & 4095, s = id & 4095;
        int t = threadIdx.x;
        a_row[t] = __bfloat162float(g_bf0[((size_t)n * LL + l) * CC + t]);
        b_col[t] = __bfloat162float(g_bf1[((size_t)n * LL + s) * CC + t]);
        __syncthreads();

        red[t] = a_row[t] * b_col[t]; __syncthreads();
        for (int off = 128; off > 0; off >>= 1) {
            if (t < off) red[t] += red[t + off];
            __syncthreads();
        }
        float e0 = __expf(red[0] * SCALEF);
        float p0 = e0 * e0 * g_invR[n * LL + l] * g_invC[n * LL + s];
        __syncthreads();

        float ir = g_invR[n * LL + l], ics = g_invC[n * LL + s];
        float m = -1e30f;
        for (int j = t; j < LL; j += 256) {
            const __nv_bfloat16* b = g_bf1 + ((size_t)n * LL + j) * CC;
            float d = 0.f;
            #pragma unroll 8
            for (int k = 0; k < CC; k++) d += a_row[k] * __bfloat162float(b[k]);
            float e = __expf(d * SCALEF);
            m = fmaxf(m, e * e * ir * g_invC[n * LL + j]);
        }
        red[t] = m; __syncthreads();
        for (int off = 128; off > 0; off >>= 1) {
            if (t < off) red[t] = fmaxf(red[t], red[t + off]);
            __syncthreads();
        }
        float rowmax = red[0]; __syncthreads();

        m = -1e30f;
        for (int j = t; j < LL; j += 256) {
            const __nv_bfloat16* a = g_bf0 + ((size_t)n * LL + j) * CC;
            float d = 0.f;
            #pragma unroll 8
            for (int k = 0; k < CC; k++) d += __bfloat162float(a[k]) * b_col[k];
            float e = __expf(d * SCALEF);
            m = fmaxf(m, e * e * g_invR[n * LL + j] * ics);
        }
        red[t] = m; __syncthreads();
        for (int off = 128; off > 0; off >>= 1) {
            if (t < off) red[t] = fmaxf(red[t], red[t + off]);
            __syncthreads();
        }
        float colmax = red[0]; __syncthreads();

        bool match = (p0 > THRV) && (p0 >= rowmax * (1.f - 1e-6f)) && (p0 >= colmax * (1.f - 1e-6f));
        if (match) {
            accum_fea_pooled(f1 + (size_t)n * LL * CC, s, g_s0p + ((size_t)n * LL + l) * 96);
            accum_fea_pooled(f0 + (size_t)n * LL * CC, l, g_s1p + ((size_t)n * LL + s) * 96);
        }
        __syncthreads();
    }
}

// ------------------------- kernel 7: pool + concat + LayerNorm --------------
__global__ void k_out(const float* __restrict__ f0, const float* __restrict__ f1,
                      const float* __restrict__ lw, const float* __restrict__ lb,
                      float* __restrict__ out) {
    __shared__ float frow[CC];
    int l = blockIdx.x, b = blockIdx.y;          // b in [0,4)
    int n = b & 1;
    const float* X  = (b < 2 ? f0 : f1) + ((size_t)n * LL + l) * CC;
    const float* sp = (b < 2 ? g_s0p : g_s1p) + ((size_t)n * LL + l) * 96;
    int t = threadIdx.x;
    frow[t] = X[t];
    __syncthreads();

    float val;
    if (t < 160) {
        int st = (t * 256) / 160, en = ((t + 1) * 256 + 159) / 160;
        float s = 0.f;
        for (int q = st; q < en; q++) s += frow[q];
        val = s / (float)(en - st);
    } else {
        val = sp[t - 160];
    }
    __syncthreads();

    frow[t] = val; __syncthreads();
    for (int off = 128; off > 0; off >>= 1) {
        if (t < off) frow[t] += frow[t + off];
        __syncthreads();
    }
    float mean = frow[0] * (1.0f / CC);
    __syncthreads();
    float d = val - mean;
    frow[t] = d * d; __syncthreads();
    for (int off = 128; off > 0; off >>= 1) {
        if (t < off) frow[t] += frow[t + off];
        __syncthreads();
    }
    float var = frow[0] * (1.0f / CC);
    float r = rsqrtf(var + 1e-5f);
    out[((size_t)b * LL + l) * CC + t] = d * r * lw[t] + lb[t];
}

// ------------------------- launch ------------------------------------------
extern "C" void kernel_launch(void* const* d_in, const int* in_sizes, int n_in,
                              void* d_out, int out_size) {
    const float* f0 = (const float*)d_in[0];
    const float* f1 = (const float*)d_in[1];
    const float* lw = (const float*)d_in[2];
    const float* lb = (const float*)d_in[3];
    float* out = (float*)d_out;
    (void)in_sizes; (void)n_in; (void)out_size;

    cudaFuncSetAttribute(k_gemm, cudaFuncAttributeMaxDynamicSharedMemorySize, 73728);

    k_zero<<<(NBATCH * LL * 96 + 511) / 512, 512>>>();
    k_convert<<<(NBATCH * LL * CC / 4 + 255) / 256, 256>>>((const float4*)f0, (const float4*)f1);
    k_gemm<<<dim3(32, 32, NBATCH), 256, 73728>>>();
    k_reduce<<<128, 256>>>();
    k_tilescan<<<(NTILES + 255) / 256, 256>>>();
    k_rescan<<<64, 256>>>();
    k_match<<<32, 256>>>(f0, f1);
    k_out<<<dim3(LL, 4), 256>>>(f0, f1, lw, lb, out);
}